// round 1
// baseline (speedup 1.0000x reference)
#include <cuda_runtime.h>
#include <cstdint>

// Furthest Point Sampling, exact-match to JAX reference.
// B=16 batches, N=32768 points, M=2048 samples.
// One cluster of 8 CTAs per batch; 4096 points/CTA resident in registers.
// Per iteration: reg update+argmax -> redux.sync warp argmax -> smem CTA
// argmax -> all-to-all DSMEM candidate exchange (double-buffered, one
// mbarrier per CTA) -> redundant 8-way local reduce -> next seed point.

constexpr int NPTS = 32768;
constexpr int MOUT = 2048;
constexpr int CS   = 8;            // cluster size (CTAs per batch)
constexpr int PCTA = NPTS / CS;    // 4096 points per CTA
constexpr int NT   = 256;          // threads per CTA
constexpr int PPT  = PCTA / NT;    // 16 points per thread
constexpr int NW   = NT / 32;      // 8 warps

struct __align__(16) ClusterShm {
    unsigned long long mbar;
    unsigned long long warp_keys[NW];
    unsigned long long slot_key[2][CS];   // double-buffered candidate slots
    unsigned long long slot_xy[2][CS];
    float              slot_z[2][CS];
    float sx[PCTA];                        // coordinate copy for winner lookup
    float sy[PCTA];
    float sz[PCTA];
};

__device__ __forceinline__ uint32_t smem_u32(const void* p) {
    return (uint32_t)__cvta_generic_to_shared(p);
}
__device__ __forceinline__ uint32_t mapa_u32(uint32_t a, uint32_t r) {
    uint32_t out;
    asm("mapa.shared::cluster.u32 %0, %1, %2;" : "=r"(out) : "r"(a), "r"(r));
    return out;
}
__device__ __forceinline__ void mbar_wait_parity_cluster(uint32_t addr, uint32_t parity) {
    asm volatile(
        "{\n\t"
        ".reg .pred P;\n\t"
        "WAITLOOP%=:\n\t"
        "mbarrier.try_wait.parity.acquire.cluster.shared::cta.b64 P, [%0], %1;\n\t"
        "@!P bra WAITLOOP%=;\n\t"
        "}"
        :: "r"(addr), "r"(parity) : "memory");
}

__global__ void __launch_bounds__(NT, 1) __cluster_dims__(CS, 1, 1)
fps_kernel(const float* __restrict__ pts, float* __restrict__ out)
{
    extern __shared__ __align__(16) char shm_raw[];
    ClusterShm* s = reinterpret_cast<ClusterShm*>(shm_raw);

    const int tid = threadIdx.x;
    uint32_t rank;
    asm("mov.u32 %0, %%cluster_ctarank;" : "=r"(rank));
    const int batch = blockIdx.x / CS;

    const float* px = pts + (size_t)batch * 3u * NPTS;
    const float* py = px + NPTS;
    const float* pz = px + 2 * NPTS;
    float* ob = out + (size_t)batch * 3u * MOUT;

    const uint32_t mbar_a = smem_u32(&s->mbar);
    if (tid == 0) {
        asm volatile("mbarrier.init.shared.b64 [%0], %1;"
                     :: "r"(mbar_a), "r"(CS) : "memory");
    }

    // Load this CTA's 4096 points into registers (+ smem copy for lookup).
    float x[PPT], y[PPT], z[PPT], d[PPT];
    const int base = (int)rank * PCTA + tid;   // global point index, k-strided
#pragma unroll
    for (int k = 0; k < PPT; ++k) {
        const int n = base + k * NT;           // coalesced
        x[k] = px[n]; y[k] = py[n]; z[k] = pz[n];
        d[k] = 1e10f;
        const int l = tid + k * NT;            // CTA-local index
        s->sx[l] = x[k]; s->sy[l] = y[k]; s->sz[l] = z[k];
    }
    // First selected point is global index 0 (CUDA FPS convention).
    float lx = px[0], ly = py[0], lz = pz[0];

    __syncthreads();
    // All mbarriers initialized cluster-wide before any remote arrive.
    asm volatile("barrier.cluster.arrive.aligned;" ::: "memory");
    asm volatile("barrier.cluster.wait.aligned;"   ::: "memory");

    const bool writer = (rank == 0u) && (tid == 0);
    const int lane = tid & 31;

    for (int j = 0; j < MOUT; ++j) {
        // Emit current selection's coordinates (this IS the gathered output).
        if (writer) { ob[j] = lx; ob[MOUT + j] = ly; ob[2 * MOUT + j] = lz; }
        if (j == MOUT - 1) break;

        // --- distance update (exact fp32, no FMA contraction: (dx^2+dy^2)+dz^2) ---
#pragma unroll
        for (int k = 0; k < PPT; ++k) {
            float dx = __fsub_rn(x[k], lx);
            float dy = __fsub_rn(y[k], ly);
            float dz = __fsub_rn(z[k], lz);
            float dd = __fadd_rn(__fadd_rn(__fmul_rn(dx, dx), __fmul_rn(dy, dy)),
                                 __fmul_rn(dz, dz));
            d[k] = fminf(d[k], dd);
        }
        // --- per-thread argmax: max tree, then first-index equality scan ---
        float bv = d[0];
#pragma unroll
        for (int k = 1; k < PPT; ++k) bv = fmaxf(bv, d[k]);
        int bk = 0;
#pragma unroll
        for (int k = PPT - 1; k >= 0; --k) {   // descending: keeps smallest k
            if (d[k] == bv) bk = k;
        }
        const int bgidx = base + bk * NT;

        // --- warp argmax via redux.sync (dist >= 0 so bits are order-preserving) ---
        const uint32_t bvbits = __float_as_uint(bv);
        const uint32_t wval = __reduce_max_sync(0xFFFFFFFFu, bvbits);
        const uint32_t cand = (bvbits == wval) ? (uint32_t)bgidx : 0xFFFFFFFFu;
        const uint32_t widx = __reduce_min_sync(0xFFFFFFFFu, cand);
        if (lane == 0) {
            // key: max value wins; tie -> max(~idx) = min idx (JAX first-occurrence)
            s->warp_keys[tid >> 5] =
                ((unsigned long long)wval << 32) |
                (unsigned long long)(0xFFFFFFFFu - widx);
        }
        __syncthreads();

        const int buf = j & 1;
        // --- CTA argmax + all-to-all candidate broadcast (tids 0..7, one per CTA) ---
        if (tid < CS) {
            unsigned long long ck = s->warp_keys[0];
#pragma unroll
            for (int w = 1; w < NW; ++w) {
                unsigned long long kk = s->warp_keys[w];
                if (kk > ck) ck = kk;
            }
            const uint32_t g = 0xFFFFFFFFu - (uint32_t)ck;      // global idx
            const int lidx = (int)g - (int)rank * PCTA;          // CTA-local idx
            const float cx = s->sx[lidx];
            const float cy = s->sy[lidx];
            const float cz = s->sz[lidx];
            const unsigned long long cxy =
                ((unsigned long long)__float_as_uint(cy) << 32) |
                (unsigned long long)__float_as_uint(cx);

            const uint32_t tr = (uint32_t)tid;                   // target CTA rank
            const uint32_t a_key = mapa_u32(smem_u32(&s->slot_key[buf][rank]), tr);
            const uint32_t a_xy  = mapa_u32(smem_u32(&s->slot_xy[buf][rank]),  tr);
            const uint32_t a_z   = mapa_u32(smem_u32(&s->slot_z[buf][rank]),   tr);
            asm volatile("st.shared::cluster.u64 [%0], %1;" :: "r"(a_key), "l"(ck)  : "memory");
            asm volatile("st.shared::cluster.u64 [%0], %1;" :: "r"(a_xy),  "l"(cxy) : "memory");
            asm volatile("st.shared::cluster.u32 [%0], %1;"
                         :: "r"(a_z), "r"(__float_as_uint(cz)) : "memory");
            const uint32_t a_mb = mapa_u32(mbar_a, tr);
            asm volatile("mbarrier.arrive.release.cluster.shared::cluster.b64 _, [%0];"
                         :: "r"(a_mb) : "memory");
        }

        // --- wait for all 8 candidates, then redundant local reduce ---
        mbar_wait_parity_cluster(mbar_a, (uint32_t)buf);

        unsigned long long gk = s->slot_key[buf][0];
        int bs = 0;
#pragma unroll
        for (int c = 1; c < CS; ++c) {
            unsigned long long kk = s->slot_key[buf][c];
            if (kk > gk) { gk = kk; bs = c; }
        }
        const unsigned long long wxy = s->slot_xy[buf][bs];
        lx = __uint_as_float((uint32_t)wxy);
        ly = __uint_as_float((uint32_t)(wxy >> 32));
        lz = s->slot_z[buf][bs];
        __syncthreads();   // protects warp_keys & slot-read vs next iteration
    }

    // No CTA exits while peers may still be touching its SMEM.
    asm volatile("barrier.cluster.arrive.aligned;" ::: "memory");
    asm volatile("barrier.cluster.wait.aligned;"   ::: "memory");
}

extern "C" void kernel_launch(void* const* d_in, const int* in_sizes, int n_in,
                              void* d_out, int out_size)
{
    (void)n_in; (void)out_size;
    const float* pts = (const float*)d_in[0];
    float* out = (float*)d_out;
    const int B = in_sizes[0] / (3 * NPTS);   // 16

    const size_t shm = sizeof(ClusterShm);    // ~49.6 KB -> needs opt-in
    cudaFuncSetAttribute(fps_kernel, cudaFuncAttributeMaxDynamicSharedMemorySize,
                         (int)shm);
    fps_kernel<<<B * CS, NT, shm>>>(pts, out);
}

// round 3
// speedup vs baseline: 1.0833x; 1.0833x over previous
#include <cuda_runtime.h>
#include <cstdint>

// Furthest Point Sampling, exact-match to JAX reference.
// B=16 batches, N=32768 points, M=2048 samples.
// One cluster of 8 CTAs per batch; 4096 points/CTA resident in registers
// (f32x2-packed). Per iteration: packed reg update + argmax -> redux.sync
// warp argmax -> smem keys -> HIGH-warp worker does CTA argmax + all-to-all
// DSMEM candidate exchange (double-buffered) -> sleep-wait on mbarrier ->
// redundant 8-way local reduce -> next seed point. No trailing syncthreads
// (release-arrive / acquire-wait chain provides the needed happens-before).

constexpr int NPTS = 32768;
constexpr int MOUT = 2048;
constexpr int CS   = 8;            // cluster size (CTAs per batch)
constexpr int PCTA = NPTS / CS;    // 4096 points per CTA
constexpr int NT   = 256;          // threads per CTA
constexpr int PPT  = PCTA / NT;    // 16 points per thread
constexpr int NPAIR = PPT / 2;     // 8 packed pairs per thread
constexpr int NW   = NT / 32;      // 8 warps

struct __align__(16) ClusterShm {
    unsigned long long mbar;
    unsigned long long warp_keys[NW];
    unsigned long long slot_key[2][CS];   // double-buffered candidate slots
    unsigned long long slot_xy[2][CS];
    float              slot_z[2][CS];
    float sx[PCTA];                        // coordinate copy for winner lookup
    float sy[PCTA];
    float sz[PCTA];
};

__device__ __forceinline__ uint32_t smem_u32(const void* p) {
    return (uint32_t)__cvta_generic_to_shared(p);
}
__device__ __forceinline__ uint32_t mapa_u32(uint32_t a, uint32_t r) {
    uint32_t out;
    asm("mapa.shared::cluster.u32 %0, %1, %2;" : "=r"(out) : "r"(a), "r"(r));
    return out;
}
// HW-sleep wait: suspendTime hint makes TRYWAIT nap instead of hot-spinning,
// so waiting warps don't steal issue slots from the worker warp.
__device__ __forceinline__ void mbar_wait_sleep(uint32_t addr, uint32_t parity) {
    asm volatile(
        "{\n\t"
        ".reg .pred P;\n\t"
        "WAITLOOP%=:\n\t"
        "mbarrier.try_wait.parity.acquire.cluster.shared::cta.b64 P, [%0], %1, 0x989680;\n\t"
        "@!P bra WAITLOOP%=;\n\t"
        "}"
        :: "r"(addr), "r"(parity) : "memory");
}
__device__ __forceinline__ unsigned long long pack2(float lo, float hi) {
    unsigned long long r;
    asm("mov.b64 %0, {%1, %2};" : "=l"(r) : "f"(lo), "f"(hi));
    return r;
}
__device__ __forceinline__ void unpack2(unsigned long long v, float& lo, float& hi) {
    asm("mov.b64 {%0, %1}, %2;" : "=f"(lo), "=f"(hi) : "l"(v));
}
__device__ __forceinline__ unsigned long long addx2(unsigned long long a, unsigned long long b) {
    unsigned long long r;
    asm("add.rn.f32x2 %0, %1, %2;" : "=l"(r) : "l"(a), "l"(b));
    return r;
}
__device__ __forceinline__ unsigned long long mulx2(unsigned long long a, unsigned long long b) {
    unsigned long long r;
    asm("mul.rn.f32x2 %0, %1, %2;" : "=l"(r) : "l"(a), "l"(b));
    return r;
}

__global__ void __launch_bounds__(NT, 1) __cluster_dims__(CS, 1, 1)
fps_kernel(const float* __restrict__ pts, float* __restrict__ out)
{
    extern __shared__ __align__(16) char shm_raw[];
    ClusterShm* s = reinterpret_cast<ClusterShm*>(shm_raw);

    const int tid = threadIdx.x;
    uint32_t rank;
    asm("mov.u32 %0, %%cluster_ctarank;" : "=r"(rank));
    const int batch = blockIdx.x / CS;

    const float* px = pts + (size_t)batch * 3u * NPTS;
    const float* py = px + NPTS;
    const float* pz = px + 2 * NPTS;
    float* ob = out + (size_t)batch * 3u * MOUT;

    const uint32_t mbar_a = smem_u32(&s->mbar);
    if (tid == 0) {
        asm volatile("mbarrier.init.shared.b64 [%0], %1;"
                     :: "r"(mbar_a), "r"(CS) : "memory");
    }

    // Load this CTA's 4096 points into packed registers (+ smem copy).
    unsigned long long X2[NPAIR], Y2[NPAIR], Z2[NPAIR];
    float d[PPT];
    const int base = (int)rank * PCTA + tid;   // global point index, k-strided
#pragma unroll
    for (int p = 0; p < NPAIR; ++p) {
        const int n0 = base + (2 * p) * NT;        // coalesced
        const int n1 = base + (2 * p + 1) * NT;
        float x0 = px[n0], x1 = px[n1];
        float y0 = py[n0], y1 = py[n1];
        float z0 = pz[n0], z1 = pz[n1];
        X2[p] = pack2(x0, x1);
        Y2[p] = pack2(y0, y1);
        Z2[p] = pack2(z0, z1);
        d[2 * p] = 1e10f; d[2 * p + 1] = 1e10f;
        const int l0 = tid + (2 * p) * NT;
        const int l1 = tid + (2 * p + 1) * NT;
        s->sx[l0] = x0; s->sy[l0] = y0; s->sz[l0] = z0;
        s->sx[l1] = x1; s->sy[l1] = y1; s->sz[l1] = z1;
    }
    // First selected point is global index 0 (CUDA FPS convention).
    float lx = px[0], ly = py[0], lz = pz[0];

    __syncthreads();
    // All mbarriers initialized cluster-wide before any remote arrive.
    asm volatile("barrier.cluster.arrive.aligned;" ::: "memory");
    asm volatile("barrier.cluster.wait.aligned;"   ::: "memory");

    const bool writer = (rank == 0u) && (tid == 0);
    const int lane = tid & 31;
    const int wid  = tid >> 5;

    for (int j = 0; j < MOUT; ++j) {
        // Emit current selection's coordinates (this IS the gathered output).
        if (writer) { ob[j] = lx; ob[MOUT + j] = ly; ob[2 * MOUT + j] = lz; }
        if (j == MOUT - 1) break;

        // --- packed distance update (exact fp32 rn, (dx^2+dy^2)+dz^2) ---
        const unsigned long long nlx2 = pack2(-lx, -lx);
        const unsigned long long nly2 = pack2(-ly, -ly);
        const unsigned long long nlz2 = pack2(-lz, -lz);
#pragma unroll
        for (int p = 0; p < NPAIR; ++p) {
            unsigned long long dx = addx2(X2[p], nlx2);
            unsigned long long dy = addx2(Y2[p], nly2);
            unsigned long long dz = addx2(Z2[p], nlz2);
            unsigned long long dd = addx2(addx2(mulx2(dx, dx), mulx2(dy, dy)),
                                          mulx2(dz, dz));
            float f0, f1; unpack2(dd, f0, f1);
            d[2 * p]     = fminf(d[2 * p],     f0);
            d[2 * p + 1] = fminf(d[2 * p + 1], f1);
        }
        // --- per-thread argmax: pairwise max tree, then first-index scan ---
        float t8[8];
#pragma unroll
        for (int i = 0; i < 8; ++i) t8[i] = fmaxf(d[2 * i], d[2 * i + 1]);
        float t4a = fmaxf(t8[0], t8[1]), t4b = fmaxf(t8[2], t8[3]);
        float t4c = fmaxf(t8[4], t8[5]), t4d = fmaxf(t8[6], t8[7]);
        float bv = fmaxf(fmaxf(t4a, t4b), fmaxf(t4c, t4d));
        int bk = 0;
#pragma unroll
        for (int k = PPT - 1; k >= 0; --k) {   // descending: keeps smallest k
            if (d[k] == bv) bk = k;
        }
        const int bgidx = base + bk * NT;

        // --- warp argmax via redux.sync (dist >= 0: bits order-preserving) ---
        const uint32_t bvbits = __float_as_uint(bv);
        const uint32_t wval = __reduce_max_sync(0xFFFFFFFFu, bvbits);
        const uint32_t cand = (bvbits == wval) ? (uint32_t)bgidx : 0xFFFFFFFFu;
        const uint32_t widx = __reduce_min_sync(0xFFFFFFFFu, cand);
        if (lane == 0) {
            // key: max value wins; tie -> max(~idx) = min idx (first occurrence)
            s->warp_keys[wid] =
                ((unsigned long long)wval << 32) |
                (unsigned long long)(0xFFFFFFFFu - widx);
        }
        __syncthreads();

        const int buf = j & 1;
        // --- CTA argmax + all-to-all broadcast, done by the HIGHEST warp so
        //     the hi-wid-first arbiter favors the critical path. Branch-free
        //     within the warp: all 32 lanes compute, lanes 0..7 do DSMEM ops
        //     via predicated asm (no divergent spin -> no deadlock risk). ---
        if (wid == NW - 1) {
            unsigned long long ck = s->warp_keys[0];   // broadcast LDS
#pragma unroll
            for (int w = 1; w < NW; ++w) {
                unsigned long long kk = s->warp_keys[w];
                if (kk > ck) ck = kk;
            }
            const uint32_t g = 0xFFFFFFFFu - (uint32_t)ck;      // global idx
            const int lidx = (int)g - (int)rank * PCTA;          // CTA-local idx
            const float cx = s->sx[lidx];
            const float cy = s->sy[lidx];
            const float cz = s->sz[lidx];
            const unsigned long long cxy =
                ((unsigned long long)__float_as_uint(cy) << 32) |
                (unsigned long long)__float_as_uint(cx);

            const uint32_t tr = (uint32_t)(lane & 7);            // target rank
            const uint32_t a_key = mapa_u32(smem_u32(&s->slot_key[buf][rank]), tr);
            const uint32_t a_xy  = mapa_u32(smem_u32(&s->slot_xy[buf][rank]),  tr);
            const uint32_t a_z   = mapa_u32(smem_u32(&s->slot_z[buf][rank]),   tr);
            const uint32_t a_mb  = mapa_u32(mbar_a, tr);
            asm volatile(
                "{\n\t"
                ".reg .pred p;\n\t"
                "setp.lt.u32 p, %0, 8;\n\t"
                "@p st.shared::cluster.u64 [%1], %4;\n\t"
                "@p st.shared::cluster.u64 [%2], %5;\n\t"
                "@p st.shared::cluster.u32 [%3], %6;\n\t"
                "@p mbarrier.arrive.release.cluster.shared::cluster.b64 _, [%7];\n\t"
                "}"
                :: "r"((uint32_t)lane), "r"(a_key), "r"(a_xy), "r"(a_z),
                   "l"(ck), "l"(cxy), "r"(__float_as_uint(cz)), "r"(a_mb)
                : "memory");
        }

        // --- sleep-wait for all 8 candidates, then redundant local reduce ---
        mbar_wait_sleep(mbar_a, (uint32_t)buf);

        unsigned long long gk = s->slot_key[buf][0];
        int bs = 0;
#pragma unroll
        for (int c = 1; c < CS; ++c) {
            unsigned long long kk = s->slot_key[buf][c];
            if (kk > gk) { gk = kk; bs = c; }
        }
        const unsigned long long wxy = s->slot_xy[buf][bs];
        lx = __uint_as_float((uint32_t)wxy);
        ly = __uint_as_float((uint32_t)(wxy >> 32));
        lz = s->slot_z[buf][bs];
        // No trailing __syncthreads: arrive.release -> try_wait.acquire chain
        // already orders next-iteration warp_keys writes and slot reuse (double
        // buffer, depth-2 gating through every CTA's next-iteration arrive).
    }

    // No CTA exits while peers may still be touching its SMEM.
    asm volatile("barrier.cluster.arrive.aligned;" ::: "memory");
    asm volatile("barrier.cluster.wait.aligned;"   ::: "memory");
}

extern "C" void kernel_launch(void* const* d_in, const int* in_sizes, int n_in,
                              void* d_out, int out_size)
{
    (void)n_in; (void)out_size;
    const float* pts = (const float*)d_in[0];
    float* out = (float*)d_out;
    const int B = in_sizes[0] / (3 * NPTS);   // 16

    const size_t shm = sizeof(ClusterShm);
    cudaFuncSetAttribute(fps_kernel, cudaFuncAttributeMaxDynamicSharedMemorySize,
                         (int)shm);
    fps_kernel<<<B * CS, NT, shm>>>(pts, out);
}